// round 7
// baseline (speedup 1.0000x reference)
#include <cuda_runtime.h>
#include <math.h>

#define NHEADS 8
#define EMB    64
#define FA     256
#define FB     256
#define BATCH  2
#define SEQ    2048
#define HFB    (NHEADS*FB)   // 2048

// ---------------- scratch (device globals; no allocations allowed) ----------
__device__ float g_q[(size_t)BATCH*NHEADS*EMB*SEQ];          // [b][h*64+e][n]  8MB
__device__ float g_k[(size_t)BATCH*NHEADS*EMB*SEQ];          // 8MB
__device__ float g_pre[(size_t)BATCH*NHEADS*SEQ*SEQ];        // [bh][q][k] 256MB (pre -> coeff in place)
__device__ float g_feat[(size_t)BATCH*SEQ*HFB];              // [b][q][h*256+f] 32MB

// ---------------- common SGEMM tile config ----------------------------------
#define BM 128
#define BN 128
#define BK 8
#define TM 8
#define TN 8
// 256 threads per block, each computes 8x8

// ---------------- tiny init --------------------------------------------------
__global__ void zero_l1_kernel(float* l1) {
    if (threadIdx.x < BATCH) l1[threadIdx.x] = 0.0f;
}

// ---------------- kernel 1: q/k embedding GEMMs ------------------------------
// C[o][n] = sum_f W[o][f] * Z[b][f][n]; M=512, N=2048, K=256
// grid: (SEQ/BN=16, 512/BM=4, 4)  z: b=z>>1, sel=z&1
__global__ __launch_bounds__(256) void embed_kernel(
    const float* __restrict__ Wa, const float* __restrict__ za,
    const float* __restrict__ Wb, const float* __restrict__ zb)
{
    const int bz = blockIdx.z;
    const int b = bz >> 1, sel = bz & 1;
    const float* __restrict__ A  = sel ? Wb : Wa;                       // [512 x 256] row-major
    const float* __restrict__ Bm = (sel ? zb : za) + (size_t)b*FA*SEQ;  // [256 x 2048] row-major
    float* __restrict__ C = (sel ? g_k : g_q) + (size_t)b*(NHEADS*EMB)*SEQ;

    __shared__ float As[BK][BM];
    __shared__ float Bs[BK][BN];

    const int tid = threadIdx.x;
    const int m0 = blockIdx.y * BM;
    const int n0 = blockIdx.x * BN;
    const int K = FA;
    const int ty = tid >> 4, tx = tid & 15;

    float acc[TM][TN] = {};

    for (int k0 = 0; k0 < K; k0 += BK) {
        // A transposed load: [M,K] row-major -> As[kk][mm]
        {
            const int mm = tid >> 1, kk = (tid & 1) * 4;
            float4 v = *(const float4*)&A[(size_t)(m0 + mm) * K + k0 + kk];
            As[kk + 0][mm] = v.x; As[kk + 1][mm] = v.y;
            As[kk + 2][mm] = v.z; As[kk + 3][mm] = v.w;
        }
        // B direct load: [K,N] row-major -> Bs[kk][nn]
        {
            const int kk = tid >> 5, nn = (tid & 31) * 4;
            *(float4*)&Bs[kk][nn] = *(const float4*)&Bm[(size_t)(k0 + kk) * SEQ + n0 + nn];
        }
        __syncthreads();
        #pragma unroll
        for (int kk = 0; kk < BK; kk++) {
            float a[TM], bb[TN];
            *(float4*)&a[0]  = *(const float4*)&As[kk][ty * TM];
            *(float4*)&a[4]  = *(const float4*)&As[kk][ty * TM + 4];
            *(float4*)&bb[0] = *(const float4*)&Bs[kk][tx * TN];
            *(float4*)&bb[4] = *(const float4*)&Bs[kk][tx * TN + 4];
            #pragma unroll
            for (int i = 0; i < TM; i++)
                #pragma unroll
                for (int j = 0; j < TN; j++)
                    acc[i][j] += a[i] * bb[j];
        }
        __syncthreads();
    }
    #pragma unroll
    for (int i = 0; i < TM; i++) {
        float* crow = &C[(size_t)(m0 + ty * TM + i) * SEQ + n0 + tx * TN];
        *(float4*)&crow[0] = make_float4(acc[i][0], acc[i][1], acc[i][2], acc[i][3]);
        *(float4*)&crow[4] = make_float4(acc[i][4], acc[i][5], acc[i][6], acc[i][7]);
    }
}

// ---------------- kernel 2: pre = 0.125 * q^T k  + |pre| accumulation --------
// A = q[b,h]: [64 x 2048] (e-major rows), B = k[b,h] same. C[qi][ki], M=N=2048, K=64.
// grid: (16, 16, 16)
__global__ __launch_bounds__(256) void pre_kernel(float* __restrict__ l1)
{
    const int bh = blockIdx.z;
    const int b = bh >> 3;
    const float* __restrict__ A  = g_q + (size_t)bh * EMB * SEQ;
    const float* __restrict__ Bm = g_k + (size_t)bh * EMB * SEQ;
    float* __restrict__ C = g_pre + (size_t)bh * SEQ * SEQ;

    __shared__ float As[BK][BM];
    __shared__ float Bs[BK][BN];
    __shared__ float red[256];

    const int tid = threadIdx.x;
    const int m0 = blockIdx.y * BM;
    const int n0 = blockIdx.x * BN;
    const int ty = tid >> 4, tx = tid & 15;

    float acc[TM][TN] = {};

    for (int k0 = 0; k0 < EMB; k0 += BK) {
        const int kk = tid >> 5, cc = (tid & 31) * 4;
        *(float4*)&As[kk][cc] = *(const float4*)&A [(size_t)(k0 + kk) * SEQ + m0 + cc];
        *(float4*)&Bs[kk][cc] = *(const float4*)&Bm[(size_t)(k0 + kk) * SEQ + n0 + cc];
        __syncthreads();
        #pragma unroll
        for (int k = 0; k < BK; k++) {
            float a[TM], bb[TN];
            *(float4*)&a[0]  = *(const float4*)&As[k][ty * TM];
            *(float4*)&a[4]  = *(const float4*)&As[k][ty * TM + 4];
            *(float4*)&bb[0] = *(const float4*)&Bs[k][tx * TN];
            *(float4*)&bb[4] = *(const float4*)&Bs[k][tx * TN + 4];
            #pragma unroll
            for (int i = 0; i < TM; i++)
                #pragma unroll
                for (int j = 0; j < TN; j++)
                    acc[i][j] += a[i] * bb[j];
        }
        __syncthreads();
    }

    float asum = 0.0f;
    #pragma unroll
    for (int i = 0; i < TM; i++) {
        float4 v0, v1;
        float vv[8];
        #pragma unroll
        for (int j = 0; j < TN; j++) {
            float v = acc[i][j] * 0.125f;
            vv[j] = v;
            asum += fabsf(v);
        }
        v0 = make_float4(vv[0], vv[1], vv[2], vv[3]);
        v1 = make_float4(vv[4], vv[5], vv[6], vv[7]);
        float* crow = &C[(size_t)(m0 + ty * TM + i) * SEQ + n0 + tx * TN];
        *(float4*)&crow[0] = v0;
        *(float4*)&crow[4] = v1;
    }

    // block-reduce |pre| and one atomic per block
    red[tid] = asum;
    __syncthreads();
    for (int s = 128; s > 0; s >>= 1) {
        if (tid < s) red[tid] += red[tid + s];
        __syncthreads();
    }
    if (tid == 0) {
        const float inv = 1.0f / ((float)NHEADS * (float)SEQ * (float)SEQ);
        atomicAdd(&l1[b], red[0] * inv);
    }
}

// ---------------- kernel 3: row softmax over keys (in place) -----------------
// grid: (SEQ, BATCH*NHEADS), 256 threads, 8 elems/thread
__global__ __launch_bounds__(256) void softmax_kernel()
{
    const int q  = blockIdx.x;
    const int bh = blockIdx.y;
    float* __restrict__ p = g_pre + ((size_t)bh * SEQ + q) * SEQ;
    const int tid = threadIdx.x;

    __shared__ float sm[256];

    float vals[8];
    float m = -1e30f;
    #pragma unroll
    for (int i = 0; i < 8; i++) {
        vals[i] = p[tid + i * 256];
        m = fmaxf(m, vals[i]);
    }
    sm[tid] = m; __syncthreads();
    for (int s = 128; s > 0; s >>= 1) {
        if (tid < s) sm[tid] = fmaxf(sm[tid], sm[tid + s]);
        __syncthreads();
    }
    m = sm[0];
    __syncthreads();

    float sum = 0.0f;
    #pragma unroll
    for (int i = 0; i < 8; i++) {
        vals[i] = __expf(vals[i] - m);
        sum += vals[i];
    }
    sm[tid] = sum; __syncthreads();
    for (int s = 128; s > 0; s >>= 1) {
        if (tid < s) sm[tid] += sm[tid + s];
        __syncthreads();
    }
    const float inv = 1.0f / sm[0];
    #pragma unroll
    for (int i = 0; i < 8; i++)
        p[tid + i * 256] = vals[i] * inv;
}

// ---------------- shared SGEMM helper: A [M,K] row-major, B [N,K] row-major --
// C[m][n] = sum_k A[m][k] * B[n][k]
__device__ __forceinline__ void sgemm_mk_nk(
    const float* __restrict__ A, int lda,
    const float* __restrict__ B, int ldb,
    float* __restrict__ C, int ldc, int K)
{
    __shared__ float As[BK][BM];
    __shared__ float Bs[BK][BN];

    const int tid = threadIdx.x;
    const int m0 = blockIdx.y * BM;
    const int n0 = blockIdx.x * BN;
    const int ty = tid >> 4, tx = tid & 15;
    const int lr = tid >> 1, lk = (tid & 1) * 4;

    float acc[TM][TN] = {};

    for (int k0 = 0; k0 < K; k0 += BK) {
        float4 va = *(const float4*)&A[(size_t)(m0 + lr) * lda + k0 + lk];
        float4 vb = *(const float4*)&B[(size_t)(n0 + lr) * ldb + k0 + lk];
        As[lk + 0][lr] = va.x; As[lk + 1][lr] = va.y;
        As[lk + 2][lr] = va.z; As[lk + 3][lr] = va.w;
        Bs[lk + 0][lr] = vb.x; Bs[lk + 1][lr] = vb.y;
        Bs[lk + 2][lr] = vb.z; Bs[lk + 3][lr] = vb.w;
        __syncthreads();
        #pragma unroll
        for (int kk = 0; kk < BK; kk++) {
            float a[TM], bb[TN];
            *(float4*)&a[0]  = *(const float4*)&As[kk][ty * TM];
            *(float4*)&a[4]  = *(const float4*)&As[kk][ty * TM + 4];
            *(float4*)&bb[0] = *(const float4*)&Bs[kk][tx * TN];
            *(float4*)&bb[4] = *(const float4*)&Bs[kk][tx * TN + 4];
            #pragma unroll
            for (int i = 0; i < TM; i++)
                #pragma unroll
                for (int j = 0; j < TN; j++)
                    acc[i][j] += a[i] * bb[j];
        }
        __syncthreads();
    }
    #pragma unroll
    for (int i = 0; i < TM; i++) {
        float* crow = &C[(size_t)(m0 + ty * TM + i) * ldc + n0 + tx * TN];
        *(float4*)&crow[0] = make_float4(acc[i][0], acc[i][1], acc[i][2], acc[i][3]);
        *(float4*)&crow[4] = make_float4(acc[i][4], acc[i][5], acc[i][6], acc[i][7]);
    }
}

// ---------------- kernel 4: feat = coeff @ v^T  ------------------------------
// per (b,h): M=2048, N=256, K=2048.  grid: (2, 16, 16)
__global__ __launch_bounds__(256) void feat_kernel(const float* __restrict__ zb)
{
    const int bh = blockIdx.z;
    const int b = bh >> 3, h = bh & 7;
    sgemm_mk_nk(g_pre + (size_t)bh * SEQ * SEQ, SEQ,
                zb + (size_t)b * FB * SEQ, SEQ,
                g_feat + (size_t)b * SEQ * HFB + h * FB, HFB, SEQ);
}

// ---------------- kernel 5: out = Feat @ W_c^T -------------------------------
// per b: M=2048, N=256, K=2048.  grid: (2, 16, 2)
__global__ __launch_bounds__(256) void out_kernel(const float* __restrict__ Wc,
                                                  float* __restrict__ out)
{
    const int b = blockIdx.z;
    sgemm_mk_nk(g_feat + (size_t)b * SEQ * HFB, HFB,
                Wc, HFB,
                out + (size_t)b * SEQ * FA, FA, HFB);
}

// ---------------- launch -----------------------------------------------------
extern "C" void kernel_launch(void* const* d_in, const int* in_sizes, int n_in,
                              void* d_out, int out_size)
{
    const float* z_a = (const float*)d_in[0];   // [2, 256, 2048]
    const float* z_b = (const float*)d_in[1];   // [2, 256, 2048]
    const float* W_a = (const float*)d_in[2];   // [512, 256]
    const float* W_b = (const float*)d_in[3];   // [512, 256]
    const float* W_c = (const float*)d_in[4];   // [256, 2048]
    float* out = (float*)d_out;                 // [2, 2048, 256] then l1 [2]
    float* l1  = out + (size_t)BATCH * SEQ * FA;

    zero_l1_kernel<<<1, 32>>>(l1);

    {
        dim3 grid(SEQ / BN, (NHEADS * EMB) / BM, BATCH * 2);
        embed_kernel<<<grid, 256>>>(W_a, z_a, W_b, z_b);
    }
    {
        dim3 grid(SEQ / BN, SEQ / BM, BATCH * NHEADS);
        pre_kernel<<<grid, 256>>>(l1);
    }
    {
        dim3 grid(SEQ, BATCH * NHEADS);
        softmax_kernel<<<grid, 256>>>();
    }
    {
        dim3 grid(FB / BN, SEQ / BM, BATCH * NHEADS);
        feat_kernel<<<grid, 256>>>(z_b);
    }
    {
        dim3 grid(FA / BN, SEQ / BM, BATCH);
        out_kernel<<<grid, 256>>>(W_c, out);
    }
}

// round 8
// speedup vs baseline: 1.0025x; 1.0025x over previous
#include <cuda_runtime.h>
#include <math.h>

#define NHEADS 8
#define EMB    64
#define FA     256
#define FB     256
#define BATCH  2
#define SEQ    2048
#define HFB    (NHEADS*FB)   // 2048

// ---------------- scratch (device globals; no allocations allowed) ----------
__device__ float g_q[(size_t)BATCH*NHEADS*EMB*SEQ];          // [b][h*64+e][n]  8MB
__device__ float g_k[(size_t)BATCH*NHEADS*EMB*SEQ];          // 8MB
__device__ float g_pre[(size_t)BATCH*NHEADS*SEQ*SEQ];        // [bh][q][k] 256MB (pre -> coeff in place)
__device__ float g_feat[(size_t)BATCH*SEQ*HFB];              // [b][q][h*256+f] 32MB

// ---------------- common SGEMM tile config ----------------------------------
#define BM 128
#define BN 128
#define BK 8
#define TM 8
#define TN 8
// 256 threads per block, each computes 8x8

// ---------------- tiny init --------------------------------------------------
__global__ void zero_l1_kernel(float* l1) {
    if (threadIdx.x < BATCH) l1[threadIdx.x] = 0.0f;
}

// ---------------- kernel 1: q/k embedding GEMMs ------------------------------
// C[o][n] = sum_f W[o][f] * Z[b][f][n]; M=512, N=2048, K=256
// grid: (SEQ/BN=16, 512/BM=4, 4)  z: b=z>>1, sel=z&1
__global__ __launch_bounds__(256) void embed_kernel(
    const float* __restrict__ Wa, const float* __restrict__ za,
    const float* __restrict__ Wb, const float* __restrict__ zb)
{
    const int bz = blockIdx.z;
    const int b = bz >> 1, sel = bz & 1;
    const float* __restrict__ A  = sel ? Wb : Wa;                       // [512 x 256] row-major
    const float* __restrict__ Bm = (sel ? zb : za) + (size_t)b*FA*SEQ;  // [256 x 2048] row-major
    float* __restrict__ C = (sel ? g_k : g_q) + (size_t)b*(NHEADS*EMB)*SEQ;

    __shared__ float As[BK][BM];
    __shared__ float Bs[BK][BN];

    const int tid = threadIdx.x;
    const int m0 = blockIdx.y * BM;
    const int n0 = blockIdx.x * BN;
    const int K = FA;
    const int ty = tid >> 4, tx = tid & 15;

    float acc[TM][TN] = {};

    for (int k0 = 0; k0 < K; k0 += BK) {
        // A transposed load: [M,K] row-major -> As[kk][mm]
        {
            const int mm = tid >> 1, kk = (tid & 1) * 4;
            float4 v = *(const float4*)&A[(size_t)(m0 + mm) * K + k0 + kk];
            As[kk + 0][mm] = v.x; As[kk + 1][mm] = v.y;
            As[kk + 2][mm] = v.z; As[kk + 3][mm] = v.w;
        }
        // B direct load: [K,N] row-major -> Bs[kk][nn]
        {
            const int kk = tid >> 5, nn = (tid & 31) * 4;
            *(float4*)&Bs[kk][nn] = *(const float4*)&Bm[(size_t)(k0 + kk) * SEQ + n0 + nn];
        }
        __syncthreads();
        #pragma unroll
        for (int kk = 0; kk < BK; kk++) {
            float a[TM], bb[TN];
            *(float4*)&a[0]  = *(const float4*)&As[kk][ty * TM];
            *(float4*)&a[4]  = *(const float4*)&As[kk][ty * TM + 4];
            *(float4*)&bb[0] = *(const float4*)&Bs[kk][tx * TN];
            *(float4*)&bb[4] = *(const float4*)&Bs[kk][tx * TN + 4];
            #pragma unroll
            for (int i = 0; i < TM; i++)
                #pragma unroll
                for (int j = 0; j < TN; j++)
                    acc[i][j] += a[i] * bb[j];
        }
        __syncthreads();
    }
    #pragma unroll
    for (int i = 0; i < TM; i++) {
        float* crow = &C[(size_t)(m0 + ty * TM + i) * SEQ + n0 + tx * TN];
        *(float4*)&crow[0] = make_float4(acc[i][0], acc[i][1], acc[i][2], acc[i][3]);
        *(float4*)&crow[4] = make_float4(acc[i][4], acc[i][5], acc[i][6], acc[i][7]);
    }
}

// ---------------- kernel 2: pre = 0.125 * q^T k  + |pre| accumulation --------
// A = q[b,h]: [64 x 2048] (e-major rows), B = k[b,h] same. C[qi][ki], M=N=2048, K=64.
// grid: (16, 16, 16)
__global__ __launch_bounds__(256) void pre_kernel(float* __restrict__ l1)
{
    const int bh = blockIdx.z;
    const int b = bh >> 3;
    const float* __restrict__ A  = g_q + (size_t)bh * EMB * SEQ;
    const float* __restrict__ Bm = g_k + (size_t)bh * EMB * SEQ;
    float* __restrict__ C = g_pre + (size_t)bh * SEQ * SEQ;

    __shared__ float As[BK][BM];
    __shared__ float Bs[BK][BN];
    __shared__ float red[256];

    const int tid = threadIdx.x;
    const int m0 = blockIdx.y * BM;
    const int n0 = blockIdx.x * BN;
    const int ty = tid >> 4, tx = tid & 15;

    float acc[TM][TN] = {};

    for (int k0 = 0; k0 < EMB; k0 += BK) {
        const int kk = tid >> 5, cc = (tid & 31) * 4;
        *(float4*)&As[kk][cc] = *(const float4*)&A [(size_t)(k0 + kk) * SEQ + m0 + cc];
        *(float4*)&Bs[kk][cc] = *(const float4*)&Bm[(size_t)(k0 + kk) * SEQ + n0 + cc];
        __syncthreads();
        #pragma unroll
        for (int k = 0; k < BK; k++) {
            float a[TM], bb[TN];
            *(float4*)&a[0]  = *(const float4*)&As[k][ty * TM];
            *(float4*)&a[4]  = *(const float4*)&As[k][ty * TM + 4];
            *(float4*)&bb[0] = *(const float4*)&Bs[k][tx * TN];
            *(float4*)&bb[4] = *(const float4*)&Bs[k][tx * TN + 4];
            #pragma unroll
            for (int i = 0; i < TM; i++)
                #pragma unroll
                for (int j = 0; j < TN; j++)
                    acc[i][j] += a[i] * bb[j];
        }
        __syncthreads();
    }

    float asum = 0.0f;
    #pragma unroll
    for (int i = 0; i < TM; i++) {
        float4 v0, v1;
        float vv[8];
        #pragma unroll
        for (int j = 0; j < TN; j++) {
            float v = acc[i][j] * 0.125f;
            vv[j] = v;
            asum += fabsf(v);
        }
        v0 = make_float4(vv[0], vv[1], vv[2], vv[3]);
        v1 = make_float4(vv[4], vv[5], vv[6], vv[7]);
        float* crow = &C[(size_t)(m0 + ty * TM + i) * SEQ + n0 + tx * TN];
        *(float4*)&crow[0] = v0;
        *(float4*)&crow[4] = v1;
    }

    // block-reduce |pre| and one atomic per block
    red[tid] = asum;
    __syncthreads();
    for (int s = 128; s > 0; s >>= 1) {
        if (tid < s) red[tid] += red[tid + s];
        __syncthreads();
    }
    if (tid == 0) {
        const float inv = 1.0f / ((float)NHEADS * (float)SEQ * (float)SEQ);
        atomicAdd(&l1[b], red[0] * inv);
    }
}

// ---------------- kernel 3: row softmax over keys (in place) -----------------
// grid: (SEQ, BATCH*NHEADS), 256 threads, 8 elems/thread
__global__ __launch_bounds__(256) void softmax_kernel()
{
    const int q  = blockIdx.x;
    const int bh = blockIdx.y;
    float* __restrict__ p = g_pre + ((size_t)bh * SEQ + q) * SEQ;
    const int tid = threadIdx.x;

    __shared__ float sm[256];

    float vals[8];
    float m = -1e30f;
    #pragma unroll
    for (int i = 0; i < 8; i++) {
        vals[i] = p[tid + i * 256];
        m = fmaxf(m, vals[i]);
    }
    sm[tid] = m; __syncthreads();
    for (int s = 128; s > 0; s >>= 1) {
        if (tid < s) sm[tid] = fmaxf(sm[tid], sm[tid + s]);
        __syncthreads();
    }
    m = sm[0];
    __syncthreads();

    float sum = 0.0f;
    #pragma unroll
    for (int i = 0; i < 8; i++) {
        vals[i] = __expf(vals[i] - m);
        sum += vals[i];
    }
    sm[tid] = sum; __syncthreads();
    for (int s = 128; s > 0; s >>= 1) {
        if (tid < s) sm[tid] += sm[tid + s];
        __syncthreads();
    }
    const float inv = 1.0f / sm[0];
    #pragma unroll
    for (int i = 0; i < 8; i++)
        p[tid + i * 256] = vals[i] * inv;
}

// ---------------- shared SGEMM helper: A [M,K] row-major, B [N,K] row-major --
// C[m][n] = sum_k A[m][k] * B[n][k]
__device__ __forceinline__ void sgemm_mk_nk(
    const float* __restrict__ A, int lda,
    const float* __restrict__ B, int ldb,
    float* __restrict__ C, int ldc, int K)
{
    __shared__ float As[BK][BM];
    __shared__ float Bs[BK][BN];

    const int tid = threadIdx.x;
    const int m0 = blockIdx.y * BM;
    const int n0 = blockIdx.x * BN;
    const int ty = tid >> 4, tx = tid & 15;
    const int lr = tid >> 1, lk = (tid & 1) * 4;

    float acc[TM][TN] = {};

    for (int k0 = 0; k0 < K; k0 += BK) {
        float4 va = *(const float4*)&A[(size_t)(m0 + lr) * lda + k0 + lk];
        float4 vb = *(const float4*)&B[(size_t)(n0 + lr) * ldb + k0 + lk];
        As[lk + 0][lr] = va.x; As[lk + 1][lr] = va.y;
        As[lk + 2][lr] = va.z; As[lk + 3][lr] = va.w;
        Bs[lk + 0][lr] = vb.x; Bs[lk + 1][lr] = vb.y;
        Bs[lk + 2][lr] = vb.z; Bs[lk + 3][lr] = vb.w;
        __syncthreads();
        #pragma unroll
        for (int kk = 0; kk < BK; kk++) {
            float a[TM], bb[TN];
            *(float4*)&a[0]  = *(const float4*)&As[kk][ty * TM];
            *(float4*)&a[4]  = *(const float4*)&As[kk][ty * TM + 4];
            *(float4*)&bb[0] = *(const float4*)&Bs[kk][tx * TN];
            *(float4*)&bb[4] = *(const float4*)&Bs[kk][tx * TN + 4];
            #pragma unroll
            for (int i = 0; i < TM; i++)
                #pragma unroll
                for (int j = 0; j < TN; j++)
                    acc[i][j] += a[i] * bb[j];
        }
        __syncthreads();
    }
    #pragma unroll
    for (int i = 0; i < TM; i++) {
        float* crow = &C[(size_t)(m0 + ty * TM + i) * ldc + n0 + tx * TN];
        *(float4*)&crow[0] = make_float4(acc[i][0], acc[i][1], acc[i][2], acc[i][3]);
        *(float4*)&crow[4] = make_float4(acc[i][4], acc[i][5], acc[i][6], acc[i][7]);
    }
}

// ---------------- kernel 4: feat = coeff @ v^T  ------------------------------
// per (b,h): M=2048, N=256, K=2048.  grid: (2, 16, 16)
__global__ __launch_bounds__(256) void feat_kernel(const float* __restrict__ zb)
{
    const int bh = blockIdx.z;
    const int b = bh >> 3, h = bh & 7;
    sgemm_mk_nk(g_pre + (size_t)bh * SEQ * SEQ, SEQ,
                zb + (size_t)b * FB * SEQ, SEQ,
                g_feat + (size_t)b * SEQ * HFB + h * FB, HFB, SEQ);
}

// ---------------- kernel 5: out = Feat @ W_c^T -------------------------------
// per b: M=2048, N=256, K=2048.  grid: (2, 16, 2)
__global__ __launch_bounds__(256) void out_kernel(const float* __restrict__ Wc,
                                                  float* __restrict__ out)
{
    const int b = blockIdx.z;
    sgemm_mk_nk(g_feat + (size_t)b * SEQ * HFB, HFB,
                Wc, HFB,
                out + (size_t)b * SEQ * FA, FA, HFB);
}

// ---------------- launch -----------------------------------------------------
extern "C" void kernel_launch(void* const* d_in, const int* in_sizes, int n_in,
                              void* d_out, int out_size)
{
    const float* z_a = (const float*)d_in[0];   // [2, 256, 2048]
    const float* z_b = (const float*)d_in[1];   // [2, 256, 2048]
    const float* W_a = (const float*)d_in[2];   // [512, 256]
    const float* W_b = (const float*)d_in[3];   // [512, 256]
    const float* W_c = (const float*)d_in[4];   // [256, 2048]
    float* out = (float*)d_out;                 // [2, 2048, 256] then l1 [2]
    float* l1  = out + (size_t)BATCH * SEQ * FA;

    zero_l1_kernel<<<1, 32>>>(l1);

    {
        dim3 grid(SEQ / BN, (NHEADS * EMB) / BM, BATCH * 2);
        embed_kernel<<<grid, 256>>>(W_a, z_a, W_b, z_b);
    }
    {
        dim3 grid(SEQ / BN, SEQ / BM, BATCH * NHEADS);
        pre_kernel<<<grid, 256>>>(l1);
    }
    {
        dim3 grid(SEQ, BATCH * NHEADS);
        softmax_kernel<<<grid, 256>>>();
    }
    {
        dim3 grid(FB / BN, SEQ / BM, BATCH * NHEADS);
        feat_kernel<<<grid, 256>>>(z_b);
    }
    {
        dim3 grid(FA / BN, SEQ / BM, BATCH);
        out_kernel<<<grid, 256>>>(W_c, out);
    }
}